// round 10
// baseline (speedup 1.0000x reference)
#include <cuda_runtime.h>
#include <cuda_bf16.h>

#define DIM     65536
#define BATCH   32
#define TILE    8192       // 2^13 amps per tile
#define THREADS 512

// Scratch (float2 = interleaved re,im). Static: no runtime alloc. 16 MB each.
__device__ float2 d_s1[BATCH * DIM];
__device__ float2 d_s2[BATCH * DIM];

// GF(2) bank swizzle for 13-bit tile index: fold bits 5..8 into bank bits with
// masks {3,6,12,17}. Verified conflict-free for all warp-lane position sets used.
__device__ __forceinline__ int SWZ(int i) {
    int x = (((i >> 5) & 1) * 3) ^ (((i >> 6) & 1) * 6)
          ^ (((i >> 7) & 1) * 12) ^ (((i >> 8) & 1) * 17);
    return i ^ x;
}

// ---- address functors (element index into float2 scratch / float input) ----
struct MapIn {        // pass1 W1 <- input:  g = (a<<3)|hv
    int base, hv;
    __device__ __forceinline__ int operator()(int a) const {
        return base + ((a << 3) | hv);
    }
};
struct MapS1Store {   // pass1 W4 -> d_s1
    int base, hv;     // hv = pass1 hv (g0..2)
    __device__ __forceinline__ int operator()(int a) const {
        return base + ((a >> 4) | (hv << 9) | ((a & 15) << 12));
    }
};
struct MapS1Load {    // pass2 W_A <- d_s1
    int base, hv;     // hv = pass2 hv (g4..6)
    __device__ __forceinline__ int operator()(int a) const {
        return base + ((a >> 4) | ((a & 15) << 9) | (hv << 13));
    }
};
struct MapS2Store {   // pass2 W_D -> d_s2
    int base, hv;     // hv = pass2 hv
    __device__ __forceinline__ int operator()(int a) const {
        return base + ((a & 15) | ((a >> 8) << 4) | (hv << 9)
                     | (((a >> 4) & 7) << 12) | (((a >> 7) & 1) << 15));
    }
};
struct MapS2Load {    // pass3 W_A <- d_s2
    int base, hv;     // hv = pass3 hv (g8..10)
    __device__ __forceinline__ int operator()(int a) const {
        return base + ((a & 15) | ((a >> 8) << 4) | (((a >> 4) & 15) << 9) | (hv << 13));
    }
};

// ---------------------------------------------------------------------------
// Per-CTA fused unitaries U = RZ*RY*RX into smem: sU[(l*16+q)*8 + k]
// ---------------------------------------------------------------------------
__device__ __forceinline__ void compute_U(const float* __restrict__ thetas, float* sU) {
    int t = threadIdx.x;
    if (t < 32) {
        int l = t >> 4, q = t & 15;
        float th0 = thetas[l * 48 + 0 * 16 + q];
        float th1 = thetas[l * 48 + 1 * 16 + q];
        float th2 = thetas[l * 48 + 2 * 16 + q];
        float c0, s0, c1, s1, cz, sz;
        sincosf(0.5f * th0, &s0, &c0);
        sincosf(0.5f * th1, &s1, &c1);
        sincosf(0.5f * th2, &sz, &cz);
        float m00r =  c1 * c0, m00i =  s1 * s0;
        float m01r = -s1 * c0, m01i = -c1 * s0;
        float m10r =  s1 * c0, m10i = -c1 * s0;
        float m11r =  c1 * c0, m11i = -s1 * s0;
        float* u = sU + (l * 16 + q) * 8;
        u[0] = m00r * cz + m00i * sz;  u[1] = m00i * cz - m00r * sz;
        u[2] = m01r * cz + m01i * sz;  u[3] = m01i * cz - m01r * sz;
        u[4] = m10r * cz - m10i * sz;  u[5] = m10i * cz + m10r * sz;
        u[6] = m11r * cz - m11i * sz;  u[7] = m11i * cz + m11r * sz;
    }
    __syncthreads();
}

// ---------------------------------------------------------------------------
// 4-bit register window over 13-bit tile index
// ---------------------------------------------------------------------------
template <int WMASK>
__device__ __forceinline__ int expand_t(int t) {
    int base = 0, tb = 0;
    #pragma unroll
    for (int b = 0; b < 13; b++) {
        if (!(WMASK & (1 << b))) { base |= ((t >> tb) & 1) << b; tb++; }
    }
    return base;
}

template <int W0, int W1, int W2, int W3>
struct Sweep4 {
    static constexpr int WMASK = (1<<W0)|(1<<W1)|(1<<W2)|(1<<W3);
    int sraw;
    float ar[16], ai[16];

    static __device__ __forceinline__ constexpr int place(int r) {
        return (((r>>0)&1)<<W0)|(((r>>1)&1)<<W1)|(((r>>2)&1)<<W2)|(((r>>3)&1)<<W3);
    }
    __device__ __forceinline__ void init() { sraw = expand_t<WMASK>((int)threadIdx.x); }

    __device__ __forceinline__ void ld(const float* sre, const float* sim) {
        init();
        #pragma unroll
        for (int r = 0; r < 16; r++) {
            int a = SWZ(sraw | place(r));
            ar[r] = sre[a]; ai[r] = sim[a];
        }
    }
    __device__ __forceinline__ void st(float* sre, float* sim) {
        #pragma unroll
        for (int r = 0; r < 16; r++) {
            int a = SWZ(sraw | place(r));
            sre[a] = ar[r]; sim[a] = ai[r];
        }
        __syncthreads();
    }
    template <class F>
    __device__ __forceinline__ void ld_in(const float* gre, const float* gim, F f) {
        init();
        #pragma unroll
        for (int r = 0; r < 16; r++) {
            int gi = f(sraw | place(r));
            ar[r] = gre[gi]; ai[r] = gim[gi];
        }
    }
    template <class F>
    __device__ __forceinline__ void ld_f2(const float2* g, F f) {
        init();
        #pragma unroll
        for (int r = 0; r < 16; r++) {
            float2 v = g[f(sraw | place(r))];
            ar[r] = v.x; ai[r] = v.y;
        }
    }
    template <class F>
    __device__ __forceinline__ void st_f2(float2* g, F f) {
        #pragma unroll
        for (int r = 0; r < 16; r++) {
            float2 v; v.x = ar[r]; v.y = ai[r];
            g[f(sraw | place(r))] = v;
        }
    }
    template <int KB>
    __device__ __forceinline__ void g1q(const float* __restrict__ u) {
        float u0=u[0],u1=u[1],u2=u[2],u3=u[3],u4=u[4],u5=u[5],u6=u[6],u7=u[7];
        #pragma unroll
        for (int p = 0; p < 8; p++) {
            int lo = p & ((1 << KB) - 1);
            int i0 = ((p >> KB) << (KB + 1)) | lo;
            int i1 = i0 | (1 << KB);
            float xr = ar[i0], xi = ai[i0], yr = ar[i1], yi = ai[i1];
            ar[i0] = u0*xr - u1*xi + u2*yr - u3*yi;
            ai[i0] = u0*xi + u1*xr + u2*yi + u3*yr;
            ar[i1] = u4*xr - u5*xi + u6*yr - u7*yi;
            ai[i1] = u4*xi + u5*xr + u6*yi + u7*yr;
        }
    }
    template <int CB, int TB>
    __device__ __forceinline__ void cx() {
        #pragma unroll
        for (int p = 0; p < 16; p++) {
            if (((p >> CB) & 1) && !((p >> TB) & 1)) {
                int q = p | (1 << TB);
                float tr = ar[p]; ar[p] = ar[q]; ar[q] = tr;
                float ti = ai[p]; ai[p] = ai[q]; ai[q] = ti;
            }
        }
    }
};

#define SMEM_FLOATS (2 * TILE + 2 * 16 * 8)

// ---------------------------------------------------------------------------
// Pass 1: in-set global bits {3..15} (local k = g k+3, 1q -> U0[12-k]);
// hv = g{0,1,2}. L1 1q g3..15; L1 chain C(15,14)..C(4,3).
// ---------------------------------------------------------------------------
__global__ void __launch_bounds__(THREADS, 2)
pass1_kernel(const float* __restrict__ thetas,
             const float* __restrict__ in_re, const float* __restrict__ in_im) {
    extern __shared__ float sm[];
    float* sre = sm; float* sim = sm + TILE; float* sU = sm + 2 * TILE;
    int b = blockIdx.x >> 3, hv = blockIdx.x & 7;

    compute_U(thetas, sU);

    { Sweep4<9,10,11,12> s;                       // g12..15
      MapIn f; f.base = b * DIM; f.hv = hv;
      s.ld_in(in_re, in_im, f);
      s.g1q<0>(sU+3*8); s.g1q<1>(sU+2*8); s.g1q<2>(sU+1*8); s.g1q<3>(sU+0*8);
      s.cx<3,2>(); s.cx<2,1>(); s.cx<1,0>();      // C(15,14),(14,13),(13,12)
      s.st(sre, sim); }
    { Sweep4<6,7,8,9> s; s.ld(sre, sim);          // g9..12
      s.g1q<0>(sU+6*8); s.g1q<1>(sU+5*8); s.g1q<2>(sU+4*8);
      s.cx<3,2>(); s.cx<2,1>(); s.cx<1,0>();      // C(12,11),(11,10),(10,9)
      s.st(sre, sim); }
    { Sweep4<3,4,5,6> s; s.ld(sre, sim);          // g6..9
      s.g1q<0>(sU+9*8); s.g1q<1>(sU+8*8); s.g1q<2>(sU+7*8);
      s.cx<3,2>(); s.cx<2,1>(); s.cx<1,0>();      // C(9,8),(8,7),(7,6)
      s.st(sre, sim); }
    { Sweep4<0,1,2,3> s; s.ld(sre, sim);          // g3..6
      s.g1q<0>(sU+12*8); s.g1q<1>(sU+11*8); s.g1q<2>(sU+10*8);
      s.cx<3,2>(); s.cx<2,1>(); s.cx<1,0>();      // C(6,5),(5,4),(4,3)
      MapS1Store f; f.base = b * DIM; f.hv = hv;
      s.st_f2(d_s1, f); }
}

// ---------------------------------------------------------------------------
// Pass 2: in-set {0,1,2,3,7..15} (locals 0..3->g0..3, 4..12->g7..15);
// hv = g{4,5,6}. L1 1q g0,1,2 + chain C(3,2),(2,1),(1,0),(0,15);
// L2 1q on set; L2 chain C(15,14)..C(8,7).
// ---------------------------------------------------------------------------
__global__ void __launch_bounds__(THREADS, 2)
pass2_kernel(const float* __restrict__ thetas) {
    extern __shared__ float sm[];
    float* sre = sm; float* sim = sm + TILE; float* sU = sm + 2 * TILE;
    int b = blockIdx.x >> 3, hv = blockIdx.x & 7;
    const float* U1 = sU + 16 * 8;

    compute_U(thetas, sU);

    { Sweep4<0,1,2,3> s;                          // locals 0..3 = g0..3
      MapS1Load f; f.base = b * DIM; f.hv = hv;
      s.ld_f2(d_s1, f);
      s.g1q<0>(sU+15*8); s.g1q<1>(sU+14*8); s.g1q<2>(sU+13*8);  // L1 1q g0,1,2
      s.cx<3,2>(); s.cx<2,1>(); s.cx<1,0>();      // L1 C(3,2),(2,1),(1,0)
      s.g1q<1>(U1+14*8); s.g1q<2>(U1+13*8); s.g1q<3>(U1+12*8);  // L2 1q g1,2,3
      s.st(sre, sim); }
    { Sweep4<0,10,11,12> s; s.ld(sre, sim);       // locals 0,10,11,12 = g0,13,14,15
      s.cx<0,3>();                                // L1 C(0,15)
      s.g1q<0>(U1+15*8);                          // L2 1q g0
      s.g1q<1>(U1+2*8); s.g1q<2>(U1+1*8); s.g1q<3>(U1+0*8);     // L2 1q g13,14,15
      s.cx<3,2>(); s.cx<2,1>();                   // L2 C(15,14),(14,13)
      s.st(sre, sim); }
    { Sweep4<7,8,9,10> s; s.ld(sre, sim);         // locals 7..10 = g10..13
      s.g1q<0>(U1+5*8); s.g1q<1>(U1+4*8); s.g1q<2>(U1+3*8);     // L2 1q g10,11,12
      s.cx<3,2>(); s.cx<2,1>(); s.cx<1,0>();      // L2 C(13,12),(12,11),(11,10)
      s.st(sre, sim); }
    { Sweep4<4,5,6,7> s; s.ld(sre, sim);          // locals 4..7 = g7..10
      s.g1q<0>(U1+8*8); s.g1q<1>(U1+7*8); s.g1q<2>(U1+6*8);     // L2 1q g7,8,9
      s.cx<3,2>(); s.cx<2,1>(); s.cx<1,0>();      // L2 C(10,9),(9,8),(8,7)
      MapS2Store f; f.base = b * DIM; f.hv = hv;
      s.st_f2(d_s2, f); }
}

// ---------------------------------------------------------------------------
// Pass 3: in-set {0..7,11..15} (locals 0..7->g0..7, 8..12->g11..15);
// hv = g{8,9,10}. L2 1q g4,5,6; L2 chain C(7,6)..C(1,0),C(0,15). |psi|^2 out.
// ---------------------------------------------------------------------------
__global__ void __launch_bounds__(THREADS, 2)
pass3_kernel(const float* __restrict__ thetas, float* __restrict__ probs) {
    extern __shared__ float sm[];
    float* sre = sm; float* sim = sm + TILE; float* sU = sm + 2 * TILE;
    int b = blockIdx.x >> 3, hv = blockIdx.x & 7;
    const float* U1 = sU + 16 * 8;

    compute_U(thetas, sU);

    { Sweep4<4,5,6,7> s;                          // g4..7
      MapS2Load f; f.base = b * DIM; f.hv = hv;
      s.ld_f2(d_s2, f);
      s.g1q<0>(U1+11*8); s.g1q<1>(U1+10*8); s.g1q<2>(U1+9*8);   // L2 1q g4,5,6
      s.cx<3,2>(); s.cx<2,1>(); s.cx<1,0>();      // L2 C(7,6),(6,5),(5,4)
      s.st(sre, sim); }
    { Sweep4<1,2,3,4> s; s.ld(sre, sim);          // g1..4
      s.cx<3,2>(); s.cx<2,1>(); s.cx<1,0>();      // L2 C(4,3),(3,2),(2,1)
      s.st(sre, sim); }
    { Sweep4<0,1,2,12> s; s.ld(sre, sim);         // g0,1,2,15
      s.cx<1,0>(); s.cx<0,3>();                   // L2 C(1,0),(0,15)
      // direct |psi|^2 store: r bits 0..2 -> g0..2 (contiguous), r bit3 -> g15
      int g_lane = (((s.sraw >> 3) & 31) << 3) | (hv << 8) | ((s.sraw >> 8) << 11);
      float4* p4 = (float4*)(probs + b * DIM + g_lane);
      float4 v;
      v.x = s.ar[0]*s.ar[0] + s.ai[0]*s.ai[0];
      v.y = s.ar[1]*s.ar[1] + s.ai[1]*s.ai[1];
      v.z = s.ar[2]*s.ar[2] + s.ai[2]*s.ai[2];
      v.w = s.ar[3]*s.ar[3] + s.ai[3]*s.ai[3];
      p4[0] = v;
      v.x = s.ar[4]*s.ar[4] + s.ai[4]*s.ai[4];
      v.y = s.ar[5]*s.ar[5] + s.ai[5]*s.ai[5];
      v.z = s.ar[6]*s.ar[6] + s.ai[6]*s.ai[6];
      v.w = s.ar[7]*s.ar[7] + s.ai[7]*s.ai[7];
      p4[1] = v;
      float4* p4h = (float4*)(probs + b * DIM + g_lane + 32768);
      v.x = s.ar[8]*s.ar[8] + s.ai[8]*s.ai[8];
      v.y = s.ar[9]*s.ar[9] + s.ai[9]*s.ai[9];
      v.z = s.ar[10]*s.ar[10] + s.ai[10]*s.ai[10];
      v.w = s.ar[11]*s.ar[11] + s.ai[11]*s.ai[11];
      p4h[0] = v;
      v.x = s.ar[12]*s.ar[12] + s.ai[12]*s.ai[12];
      v.y = s.ar[13]*s.ar[13] + s.ai[13]*s.ai[13];
      v.z = s.ar[14]*s.ar[14] + s.ai[14]*s.ai[14];
      v.w = s.ar[15]*s.ar[15] + s.ai[15]*s.ai[15];
      p4h[1] = v; }
}

extern "C" void kernel_launch(void* const* d_in, const int* in_sizes, int n_in,
                              void* d_out, int out_size) {
    const float* thetas = (const float*)d_in[0];
    const float* st_re  = (const float*)d_in[1];
    const float* st_im  = (const float*)d_in[2];
    float* probs = (float*)d_out;

    const int SMEM = SMEM_FLOATS * sizeof(float);  // 64 KB + 1 KB
    cudaFuncSetAttribute(pass1_kernel, cudaFuncAttributeMaxDynamicSharedMemorySize, SMEM);
    cudaFuncSetAttribute(pass2_kernel, cudaFuncAttributeMaxDynamicSharedMemorySize, SMEM);
    cudaFuncSetAttribute(pass3_kernel, cudaFuncAttributeMaxDynamicSharedMemorySize, SMEM);

    dim3 grid(BATCH * 8);   // 256 CTAs, 2 per SM resident
    pass1_kernel<<<grid, THREADS, SMEM>>>(thetas, st_re, st_im);
    pass2_kernel<<<grid, THREADS, SMEM>>>(thetas);
    pass3_kernel<<<grid, THREADS, SMEM>>>(thetas, probs);
}